// round 6
// baseline (speedup 1.0000x reference)
#include <cuda_runtime.h>
#include <cuda_bf16.h>

// Fixed problem constants
#define PH 7
#define PW 7
#define C_CH 256
#define H_FEAT 200
#define W_FEAT 272
#define HW (H_FEAT*W_FEAT)
#define SCALE 0.25f

#define CH_PER_BLOCK 16
#define CHUNKS (C_CH / CH_PER_BLOCK)   // 16
#define NTHREADS 224                   // 7 warps = 7 bin rows

__global__ __launch_bounds__(NTHREADS) void roi_align_lane_split(
    const float* __restrict__ feat,
    const float* __restrict__ rois,
    float* __restrict__ out,
    int n_rois)
{
    // Consecutive blocks share a channel chunk -> waves reuse one ~7MB slice in L2.
    const int roi   = blockIdx.x % n_rois;
    const int chunk = blockIdx.x / n_rois;
    const int c0    = chunk * CH_PER_BLOCK;

    const int t    = threadIdx.x;
    const int wid  = t >> 5;            // bin row 0..6
    const int lane = t & 31;
    const int sx   = lane & 15;         // sample col 0..13 (14,15 idle)
    const bool active = (sx < 14);

    // ---- per-ROI setup ----
    const float* r = rois + roi * 5;
    const int   b   = (int)r[0];
    const float swc = r[1] * SCALE;
    const float shc = r[2] * SCALE;
    const float ewc = r[3] * SCALE;
    const float ehc = r[4] * SCALE;
    const float bin_w = fmaxf(ewc - swc, 1.0f) / PW;
    const float bin_h = fmaxf(ehc - shc, 1.0f) / PH;

    // x sample for this lane's column; lane<16 carries x-low corner, lane>=16 x-high.
    float x  = swc + ((float)sx + 0.5f) * 0.5f * bin_w;
    float vx = (x > -1.0f && x < (float)W_FEAT) ? 1.0f : 0.0f;
    float xc = fminf(fmaxf(x, 0.0f), (float)(W_FEAT - 1));
    int   xl = (int)floorf(xc);
    int   xh = min(xl + 1, W_FEAT - 1);
    float lx = xc - (float)xl;
    const int   xcol = (lane < 16) ? xl : xh;
    float wx = ((lane < 16) ? (1.0f - lx) : lx) * vx;
    if (!active) wx = 0.0f;

    // two sample rows of this bin row (uniform across warp)
    const int sy0 = wid * 2;
    float y0  = shc + ((float)sy0 + 0.5f) * 0.5f * bin_h;
    float vy0 = (y0 > -1.0f && y0 < (float)H_FEAT) ? 1.0f : 0.0f;
    float yc0 = fminf(fmaxf(y0, 0.0f), (float)(H_FEAT - 1));
    int   yl0 = (int)floorf(yc0);
    float ly0 = yc0 - (float)yl0;
    const int ol0 = yl0 * W_FEAT;
    const int oh0 = min(yl0 + 1, H_FEAT - 1) * W_FEAT;
    const float wly0 = ly0 * vy0;
    const float why0 = (1.0f - ly0) * vy0;

    const int sy1 = sy0 + 1;
    float y1  = shc + ((float)sy1 + 0.5f) * 0.5f * bin_h;
    float vy1 = (y1 > -1.0f && y1 < (float)H_FEAT) ? 1.0f : 0.0f;
    float yc1 = fminf(fmaxf(y1, 0.0f), (float)(H_FEAT - 1));
    int   yl1 = (int)floorf(yc1);
    float ly1 = yc1 - (float)yl1;
    const int ol1 = yl1 * W_FEAT;
    const int oh1 = min(yl1 + 1, H_FEAT - 1) * W_FEAT;
    const float wly1 = ly1 * vy1;
    const float why1 = (1.0f - ly1) * vy1;

    const float* f0 = feat + ((long)b * C_CH + c0) * HW;

    const bool writer = (lane < 14) && ((lane & 1) == 0);
    const long obase = ((long)roi * C_CH + c0) * (PH * PW) + wid * PW + (lane >> 1);

    #pragma unroll 8
    for (int ch = 0; ch < CH_PER_BLOCK; ch++) {
        const float* f = f0 + ch * HW;
        float a0 = 0.f, b0 = 0.f, a1 = 0.f, b1 = 0.f;
        if (active) {
            a0 = __ldg(f + ol0 + xcol);   // row yl(sy0), this lane's x corner
            b0 = __ldg(f + oh0 + xcol);   // row yh(sy0)
            a1 = __ldg(f + ol1 + xcol);   // row yl(sy1)
            b1 = __ldg(f + oh1 + xcol);   // row yh(sy1)
        }
        // y-interp + sum over the bin's two sample rows (linear, so fold early)
        float s = why0 * a0 + wly0 * b0 + why1 * a1 + wly1 * b1;
        float v = wx * s;
        // fold x-high corner (lanes 16..29) into x-low lanes (0..13)
        v += __shfl_down_sync(0xffffffffu, v, 16);
        // fold the bin's x-sample pair
        v += __shfl_xor_sync(0xffffffffu, v, 1);
        if (writer) out[obase + ch * (PH * PW)] = 0.25f * v;
    }
}

extern "C" void kernel_launch(void* const* d_in, const int* in_sizes, int n_in,
                              void* d_out, int out_size) {
    const float* feat = (const float*)d_in[0];
    const float* rois = (const float*)d_in[1];
    float* out = (float*)d_out;

    int n_rois = in_sizes[1] / 5;
    int blocks = n_rois * CHUNKS;
    roi_align_lane_split<<<blocks, NTHREADS>>>(feat, rois, out, n_rois);
}

// round 8
// speedup vs baseline: 1.8555x; 1.8555x over previous
#include <cuda_runtime.h>
#include <cuda_bf16.h>

// Fixed problem constants
#define PH 7
#define PW 7
#define C_CH 256
#define H_FEAT 200
#define W_FEAT 272
#define HW (H_FEAT*W_FEAT)
#define SCALE 0.25f

#define CH_PER_BLOCK 16
#define CHUNKS (C_CH / CH_PER_BLOCK)   // 16
#define NTHREADS 224                   // 7 warps = 7 bin rows
#define CB 4                           // channels batched per inner iteration

__global__ __launch_bounds__(NTHREADS, 6) void roi_align_batch(
    const float* __restrict__ feat,
    const float* __restrict__ rois,
    float* __restrict__ out,
    int n_rois)
{
    // Consecutive blocks share a channel chunk -> waves reuse one ~7MB slice in L2.
    const int roi   = blockIdx.x % n_rois;
    const int chunk = blockIdx.x / n_rois;
    const int c0    = chunk * CH_PER_BLOCK;

    const int t    = threadIdx.x;
    const int wid  = t >> 5;            // bin row 0..6
    const int lane = t & 31;
    const int sx   = lane & 15;         // sample col (14,15 idle -> clamped)
    const int sxe  = min(sx, 13);       // clamped: idle lanes alias lane 13's sectors

    // ---- per-ROI setup ----
    const float* r = rois + roi * 5;
    const int   b   = (int)r[0];
    const float swc = r[1] * SCALE;
    const float shc = r[2] * SCALE;
    const float ewc = r[3] * SCALE;
    const float ehc = r[4] * SCALE;
    const float bin_w = fmaxf(ewc - swc, 1.0f) / PW;
    const float bin_h = fmaxf(ehc - shc, 1.0f) / PH;

    // x sample; lane<16 carries x-low corner, lane>=16 x-high.
    float x  = swc + ((float)sxe + 0.5f) * 0.5f * bin_w;
    float vx = (x > -1.0f && x < (float)W_FEAT) ? 1.0f : 0.0f;
    float xc = fminf(fmaxf(x, 0.0f), (float)(W_FEAT - 1));
    int   xl = (int)floorf(xc);
    int   xh = min(xl + 1, W_FEAT - 1);
    float lx = xc - (float)xl;
    const int   xcol = (lane < 16) ? xl : xh;
    float wx = ((lane < 16) ? (1.0f - lx) : lx) * vx;
    if (sx >= 14) wx = 0.0f;            // idle lanes contribute 0 (loads still issue, harmless)

    // two sample rows of this bin row (uniform across warp)
    const int sy0 = wid * 2;
    float y0  = shc + ((float)sy0 + 0.5f) * 0.5f * bin_h;
    float vy0 = (y0 > -1.0f && y0 < (float)H_FEAT) ? 1.0f : 0.0f;
    float yc0 = fminf(fmaxf(y0, 0.0f), (float)(H_FEAT - 1));
    int   yl0 = (int)floorf(yc0);
    float ly0 = yc0 - (float)yl0;
    const int ol0 = yl0 * W_FEAT;
    const int oh0 = min(yl0 + 1, H_FEAT - 1) * W_FEAT;
    const float wly0 = ly0 * vy0;
    const float why0 = (1.0f - ly0) * vy0;

    float y1  = shc + ((float)(sy0 + 1) + 0.5f) * 0.5f * bin_h;
    float vy1 = (y1 > -1.0f && y1 < (float)H_FEAT) ? 1.0f : 0.0f;
    float yc1 = fminf(fmaxf(y1, 0.0f), (float)(H_FEAT - 1));
    int   yl1 = (int)floorf(yc1);
    float ly1 = yc1 - (float)yl1;
    const int ol1 = yl1 * W_FEAT;
    const int oh1 = min(yl1 + 1, H_FEAT - 1) * W_FEAT;
    const float wly1 = ly1 * vy1;
    const float why1 = (1.0f - ly1) * vy1;

    const float* fb = feat + ((long)b * C_CH + c0) * HW + xcol;

    const bool writer = (lane < 14) && ((lane & 1) == 0);
    const long obase = ((long)roi * C_CH + c0) * (PH * PW) + wid * PW + (lane >> 1);

    #pragma unroll
    for (int cc = 0; cc < CH_PER_BLOCK; cc += CB) {
        float a0[CB], b0[CB], a1[CB], b1[CB];
        // Batched branch-free loads: 4*CB = 16 outstanding LDGs per warp
        #pragma unroll
        for (int k = 0; k < CB; k++) {
            const float* f = fb + (cc + k) * HW;
            a0[k] = __ldg(f + ol0);   // row yl(sy0), this lane's x corner
            b0[k] = __ldg(f + oh0);   // row yh(sy0)
            a1[k] = __ldg(f + ol1);   // row yl(sy1)
            b1[k] = __ldg(f + oh1);   // row yh(sy1)
        }
        float v[CB];
        #pragma unroll
        for (int k = 0; k < CB; k++) {
            float s = why0 * a0[k] + wly0 * b0[k] + why1 * a1[k] + wly1 * b1[k];
            v[k] = wx * s;
        }
        // 4 independent shfl chains overlap their latency
        #pragma unroll
        for (int k = 0; k < CB; k++) {
            v[k] += __shfl_down_sync(0xffffffffu, v[k], 16);  // fold x-high corner
            v[k] += __shfl_xor_sync(0xffffffffu, v[k], 1);    // fold x-sample pair
        }
        if (writer) {
            #pragma unroll
            for (int k = 0; k < CB; k++)
                out[obase + (cc + k) * (PH * PW)] = 0.25f * v[k];
        }
    }
}

extern "C" void kernel_launch(void* const* d_in, const int* in_sizes, int n_in,
                              void* d_out, int out_size) {
    const float* feat = (const float*)d_in[0];
    const float* rois = (const float*)d_in[1];
    float* out = (float*)d_out;

    int n_rois = in_sizes[1] / 5;
    int blocks = n_rois * CHUNKS;
    roi_align_batch<<<blocks, NTHREADS>>>(feat, rois, out, n_rois);
}

// round 9
// speedup vs baseline: 2.0155x; 1.0862x over previous
#include <cuda_runtime.h>
#include <cuda_bf16.h>

// Fixed problem constants
#define PH 7
#define PW 7
#define C_CH 256
#define H_FEAT 200
#define W_FEAT 272
#define HW (H_FEAT*W_FEAT)
#define SCALE 0.25f

#define CH_PER_BLOCK 32
#define CHUNKS (C_CH / CH_PER_BLOCK)   // 8
#define NTHREADS 224                   // 7 warps = 7 bin rows
#define CB 8                           // channels batched per inner iteration

__global__ __launch_bounds__(NTHREADS, 4) void roi_align_batch8(
    const float* __restrict__ feat,
    const float* __restrict__ rois,
    float* __restrict__ out,
    int n_rois)
{
    // Consecutive blocks share a channel chunk -> waves reuse one ~14MB slice in L2.
    const int roi   = blockIdx.x % n_rois;
    const int chunk = blockIdx.x / n_rois;
    const int c0    = chunk * CH_PER_BLOCK;

    const int t    = threadIdx.x;
    const int wid  = t >> 5;            // bin row 0..6
    const int lane = t & 31;
    const int sx   = lane & 15;         // sample col (14,15 idle -> clamped)
    const int sxe  = min(sx, 13);       // idle lanes alias lane 13's sectors (free)

    // ---- per-ROI setup ----
    const float* r = rois + roi * 5;
    const int   b   = (int)r[0];
    const float swc = r[1] * SCALE;
    const float shc = r[2] * SCALE;
    const float ewc = r[3] * SCALE;
    const float ehc = r[4] * SCALE;
    const float bin_w = fmaxf(ewc - swc, 1.0f) / PW;
    const float bin_h = fmaxf(ehc - shc, 1.0f) / PH;

    // x sample; lane<16 carries x-low corner, lane>=16 x-high.
    float x  = swc + ((float)sxe + 0.5f) * 0.5f * bin_w;
    float vx = (x > -1.0f && x < (float)W_FEAT) ? 1.0f : 0.0f;
    float xc = fminf(fmaxf(x, 0.0f), (float)(W_FEAT - 1));
    int   xl = (int)floorf(xc);
    int   xh = min(xl + 1, W_FEAT - 1);
    float lx = xc - (float)xl;
    const int   xcol = (lane < 16) ? xl : xh;
    float wx = ((lane < 16) ? (1.0f - lx) : lx) * vx;
    if (sx >= 14) wx = 0.0f;            // idle lanes contribute 0

    // two sample rows of this bin row (uniform across warp)
    const int sy0 = wid * 2;
    float y0  = shc + ((float)sy0 + 0.5f) * 0.5f * bin_h;
    float vy0 = (y0 > -1.0f && y0 < (float)H_FEAT) ? 1.0f : 0.0f;
    float yc0 = fminf(fmaxf(y0, 0.0f), (float)(H_FEAT - 1));
    int   yl0 = (int)floorf(yc0);
    float ly0 = yc0 - (float)yl0;
    const int ol0 = yl0 * W_FEAT;
    const int oh0 = min(yl0 + 1, H_FEAT - 1) * W_FEAT;
    const float wly0 = ly0 * vy0;
    const float why0 = (1.0f - ly0) * vy0;

    float y1  = shc + ((float)(sy0 + 1) + 0.5f) * 0.5f * bin_h;
    float vy1 = (y1 > -1.0f && y1 < (float)H_FEAT) ? 1.0f : 0.0f;
    float yc1 = fminf(fmaxf(y1, 0.0f), (float)(H_FEAT - 1));
    int   yl1 = (int)floorf(yc1);
    float ly1 = yc1 - (float)yl1;
    const int ol1 = yl1 * W_FEAT;
    const int oh1 = min(yl1 + 1, H_FEAT - 1) * W_FEAT;
    const float wly1 = ly1 * vy1;
    const float why1 = (1.0f - ly1) * vy1;

    const float* fb = feat + ((long)b * C_CH + c0) * HW + xcol;

    const bool writer = (lane < 14) && ((lane & 1) == 0);
    const long obase = ((long)roi * C_CH + c0) * (PH * PW) + wid * PW + (lane >> 1);

    #pragma unroll
    for (int cc = 0; cc < CH_PER_BLOCK; cc += CB) {
        float a0[CB], b0[CB], a1[CB], b1[CB];
        // Batched branch-free loads: 4*CB = 32 outstanding LDGs per warp
        #pragma unroll
        for (int k = 0; k < CB; k++) {
            const float* f = fb + (cc + k) * HW;
            a0[k] = __ldg(f + ol0);   // row yl(sy0)
            b0[k] = __ldg(f + oh0);   // row yh(sy0)
            a1[k] = __ldg(f + ol1);   // row yl(sy1)
            b1[k] = __ldg(f + oh1);   // row yh(sy1)
        }
        float v[CB];
        #pragma unroll
        for (int k = 0; k < CB; k++) {
            float s = why0 * a0[k] + wly0 * b0[k] + why1 * a1[k] + wly1 * b1[k];
            v[k] = wx * s;
        }
        // 8 independent shfl chains overlap their latency
        #pragma unroll
        for (int k = 0; k < CB; k++) {
            v[k] += __shfl_down_sync(0xffffffffu, v[k], 16);  // fold x-high corner
            v[k] += __shfl_xor_sync(0xffffffffu, v[k], 1);    // fold x-sample pair
        }
        if (writer) {
            #pragma unroll
            for (int k = 0; k < CB; k++)
                out[obase + (cc + k) * (PH * PW)] = 0.25f * v[k];
        }
    }
}

extern "C" void kernel_launch(void* const* d_in, const int* in_sizes, int n_in,
                              void* d_out, int out_size) {
    const float* feat = (const float*)d_in[0];
    const float* rois = (const float*)d_in[1];
    float* out = (float*)d_out;

    int n_rois = in_sizes[1] / 5;
    int blocks = n_rois * CHUNKS;
    roi_align_batch8<<<blocks, NTHREADS>>>(feat, rois, out, n_rois);
}

// round 10
// speedup vs baseline: 2.0199x; 1.0022x over previous
#include <cuda_runtime.h>
#include <cuda_bf16.h>

// Fixed problem constants
#define PH 7
#define PW 7
#define C_CH 256
#define H_FEAT 200
#define W_FEAT 272
#define HW (H_FEAT*W_FEAT)
#define SCALE 0.25f

#define CH_PER_BLOCK 32
#define CHUNKS (C_CH / CH_PER_BLOCK)   // 8
#define NTHREADS 224                   // 7 warps = 7 bin rows
#define CB 8                           // channels batched per inner iteration (4 pairs)

__global__ __launch_bounds__(NTHREADS, 4) void roi_align_pairfold(
    const float* __restrict__ feat,
    const float* __restrict__ rois,
    float* __restrict__ out,
    int n_rois)
{
    // Consecutive blocks share a channel chunk -> waves reuse one ~14MB slice in L2.
    const int roi   = blockIdx.x % n_rois;
    const int chunk = blockIdx.x / n_rois;
    const int c0    = chunk * CH_PER_BLOCK;

    const int t    = threadIdx.x;
    const int wid  = t >> 5;            // bin row 0..6
    const int lane = t & 31;
    const int sx   = lane & 15;         // sample col (14,15 idle -> clamped)
    const int sxe  = min(sx, 13);       // idle lanes alias lane 13's sectors (free)
    const bool hi16 = (lane & 16) != 0; // x-high corner half

    // ---- per-ROI setup ----
    const float* r = rois + roi * 5;
    const int   b   = (int)r[0];
    const float swc = r[1] * SCALE;
    const float shc = r[2] * SCALE;
    const float ewc = r[3] * SCALE;
    const float ehc = r[4] * SCALE;
    const float bin_w = fmaxf(ewc - swc, 1.0f) / PW;
    const float bin_h = fmaxf(ehc - shc, 1.0f) / PH;

    // x sample; lanes<16 carry x-low corner, lanes>=16 x-high.
    float x  = swc + ((float)sxe + 0.5f) * 0.5f * bin_w;
    float vx = (x > -1.0f && x < (float)W_FEAT) ? 1.0f : 0.0f;
    float xc = fminf(fmaxf(x, 0.0f), (float)(W_FEAT - 1));
    int   xl = (int)floorf(xc);
    int   xh = min(xl + 1, W_FEAT - 1);
    float lx = xc - (float)xl;
    const int   xcol = hi16 ? xh : xl;
    float wx = (hi16 ? lx : (1.0f - lx)) * vx;
    if (sx >= 14) wx = 0.0f;            // idle lanes contribute 0

    // two sample rows of this bin row (uniform across warp)
    const int sy0 = wid * 2;
    float y0  = shc + ((float)sy0 + 0.5f) * 0.5f * bin_h;
    float vy0 = (y0 > -1.0f && y0 < (float)H_FEAT) ? 1.0f : 0.0f;
    float yc0 = fminf(fmaxf(y0, 0.0f), (float)(H_FEAT - 1));
    int   yl0 = (int)floorf(yc0);
    float ly0 = yc0 - (float)yl0;
    const int ol0 = yl0 * W_FEAT;
    const int oh0 = min(yl0 + 1, H_FEAT - 1) * W_FEAT;
    const float wly0 = ly0 * vy0;
    const float why0 = (1.0f - ly0) * vy0;

    float y1  = shc + ((float)(sy0 + 1) + 0.5f) * 0.5f * bin_h;
    float vy1 = (y1 > -1.0f && y1 < (float)H_FEAT) ? 1.0f : 0.0f;
    float yc1 = fminf(fmaxf(y1, 0.0f), (float)(H_FEAT - 1));
    int   yl1 = (int)floorf(yc1);
    float ly1 = yc1 - (float)yl1;
    const int ol1 = yl1 * W_FEAT;
    const int oh1 = min(yl1 + 1, H_FEAT - 1) * W_FEAT;
    const float wly1 = ly1 * vy1;
    const float why1 = (1.0f - ly1) * vy1;

    const float* fb = feat + ((long)b * C_CH + c0) * HW + xcol;

    // Writers: even lanes of each half; low half writes channel pair-A, high half pair-B.
    const bool writer = ((lane & 1) == 0) && ((lane & 15) < 14);
    // lane>>4 = which channel of the pair this lane's half owns after the folds
    const long obaseL = ((long)roi * C_CH + c0 + (lane >> 4)) * (PH * PW)
                      + wid * PW + ((lane & 15) >> 1);

    #pragma unroll
    for (int cc = 0; cc < CH_PER_BLOCK; cc += CB) {
        float a0[CB], b0[CB], a1[CB], b1[CB];
        // Batched branch-free loads: 4*CB = 32 outstanding LDGs per warp
        #pragma unroll
        for (int k = 0; k < CB; k++) {
            const float* f = fb + (cc + k) * HW;
            a0[k] = __ldg(f + ol0);   // row yl(sy0)
            b0[k] = __ldg(f + oh0);   // row yh(sy0)
            a1[k] = __ldg(f + ol1);   // row yl(sy1)
            b1[k] = __ldg(f + oh1);   // row yh(sy1)
        }
        // Process channels in pairs: one shfl per fold serves both channels.
        #pragma unroll
        for (int k = 0; k < CB; k += 2) {
            float sA = why0 * a0[k]   + wly0 * b0[k]   + why1 * a1[k]   + wly1 * b1[k];
            float sB = why0 * a0[k+1] + wly0 * b0[k+1] + why1 * a1[k+1] + wly1 * b1[k+1];
            float vA = wx * sA;
            float vB = wx * sB;
            // corner fold (x-low + x-high), channel-swapped across half-warps:
            // lanes<16 end up with chA's corner sum, lanes>=16 with chB's.
            float sel = hi16 ? vA : vB;
            float tt  = __shfl_xor_sync(0xffffffffu, sel, 16);
            float v2  = (hi16 ? vB : vA) + tt;
            // bin's x-sample pair fold (works for whichever channel the lane holds)
            float uu  = __shfl_xor_sync(0xffffffffu, v2, 1);
            float v3  = v2 + uu;
            if (writer) out[obaseL + (cc + k) * (PH * PW)] = 0.25f * v3;
        }
    }
}

extern "C" void kernel_launch(void* const* d_in, const int* in_sizes, int n_in,
                              void* d_out, int out_size) {
    const float* feat = (const float*)d_in[0];
    const float* rois = (const float*)d_in[1];
    float* out = (float*)d_out;

    int n_rois = in_sizes[1] / 5;
    int blocks = n_rois * CHUNKS;
    roi_align_pairfold<<<blocks, NTHREADS>>>(feat, rois, out, n_rois);
}